// round 10
// baseline (speedup 1.0000x reference)
#include <cuda_runtime.h>
#include <math.h>
#include <stdint.h>

#define E_DIM 1024
#define B_DIM 8192
#define NROWS (B_DIM * 2)          // 16384
#define HID 2048

// ---------------- scratch (device globals; no allocations allowed) ----------
__device__ float g_xs [(size_t)NROWS * E_DIM];      // ln1 output (tf32-rounded)
__device__ float g_qkv[(size_t)NROWS * 3 * E_DIM];  // fused q|k|v, row stride 3072
__device__ float g_cc [(size_t)NROWS * E_DIM];      // attention concat (tf32-rounded)
__device__ float g_o1 [(size_t)NROWS * E_DIM];      // input + res (full fp32)
__device__ float g_os [(size_t)NROWS * E_DIM];      // ln2 output (tf32-rounded)
__device__ float g_h0 [(size_t)B_DIM * HID];        // ffn hidden s=0
__device__ float g_h1 [(size_t)B_DIM * HID];        // ffn hidden s=1
__device__ float g_wr [(size_t)12 * 1024 * 1024];   // tf32-rounded weights

__device__ __forceinline__ uint32_t f2tf(float f) {
    uint32_t r;
    asm volatile("cvt.rna.tf32.f32 %0, %1;" : "=r"(r) : "f"(f));
    return r;
}
__device__ __forceinline__ float rtf(float f) { return __uint_as_float(f2tf(f)); }

// ---------------- fused weight rounding: 12M floats in one launch -----------
// dst layout: [0,1M)Wq [1M,2M)Wk [2M,3M)Wv [3M,4M)Wo [4M,6M)f1w1 [6M,8M)f1w2
//             [8M,10M)f2w1 [10M,12M)f2w2   (1M = 1024*1024)
__global__ void round_all(const float* __restrict__ Wq, const float* __restrict__ Wk,
                          const float* __restrict__ Wv, const float* __restrict__ Wo,
                          const float* __restrict__ f1w1, const float* __restrict__ f1w2,
                          const float* __restrict__ f2w1, const float* __restrict__ f2w2,
                          float* __restrict__ dst) {
    const size_t M1 = 1024 * 1024;
    size_t i4 = (size_t)blockIdx.x * 256 + threadIdx.x;   // float4 index
    size_t i = i4 * 4;                                    // element index < 12M
    const float* s; size_t off;
    if      (i <  1 * M1) { s = Wq;   off = 0; }
    else if (i <  2 * M1) { s = Wk;   off = 1 * M1; }
    else if (i <  3 * M1) { s = Wv;   off = 2 * M1; }
    else if (i <  4 * M1) { s = Wo;   off = 3 * M1; }
    else if (i <  6 * M1) { s = f1w1; off = 4 * M1; }
    else if (i <  8 * M1) { s = f1w2; off = 6 * M1; }
    else if (i < 10 * M1) { s = f2w1; off = 8 * M1; }
    else                  { s = f2w2; off = 10 * M1; }
    float4 v = *reinterpret_cast<const float4*>(s + (i - off));
    v.x = rtf(v.x); v.y = rtf(v.y); v.z = rtf(v.z); v.w = rtf(v.w);
    *reinterpret_cast<float4*>(dst + i) = v;
}

// ---------------- LayerNorm over joint (S=2, E=1024) = 2048 elems ----------
__global__ void ln_kernel(const float* __restrict__ x, const float* __restrict__ w,
                          const float* __restrict__ bb, float* __restrict__ y) {
    int b = blockIdx.x;
    int tid = threadIdx.x;
    const float* xr = x + (size_t)b * 2048;
    float v[8];
    float s = 0.f, s2 = 0.f;
#pragma unroll
    for (int i = 0; i < 8; i++) {
        float t = xr[tid + 256 * i];
        v[i] = t; s += t; s2 += t * t;
    }
#pragma unroll
    for (int o = 16; o; o >>= 1) {
        s  += __shfl_xor_sync(0xFFFFFFFFu, s,  o);
        s2 += __shfl_xor_sync(0xFFFFFFFFu, s2, o);
    }
    __shared__ float rs[8], rs2[8];
    __shared__ float mean_s, rstd_s;
    if ((tid & 31) == 0) { rs[tid >> 5] = s; rs2[tid >> 5] = s2; }
    __syncthreads();
    if (tid == 0) {
        float a = 0.f, a2 = 0.f;
#pragma unroll
        for (int i = 0; i < 8; i++) { a += rs[i]; a2 += rs2[i]; }
        float m = a * (1.f / 2048.f);
        float var = a2 * (1.f / 2048.f) - m * m;
        mean_s = m;
        rstd_s = rsqrtf(var + 1e-5f);
    }
    __syncthreads();
    float m = mean_s, r = rstd_s;
    float* yr = y + (size_t)b * 2048;
#pragma unroll
    for (int i = 0; i < 8; i++) {
        int j = tid + 256 * i;
        yr[j] = rtf((v[i] - m) * r * w[j] + bb[j]);
    }
}

// ---------------- Attention (S=2, H=16, NH=64), reads fused qkv -------------
// qkv row (2b+s) stride 3072: [q 0..1023 | k 1024..2047 | v 2048..3071]
__global__ void attn_kernel(const float* __restrict__ QKV, float* __restrict__ O) {
    int b = blockIdx.x;
    int tid = threadIdx.x;
    __shared__ float sQ[2048], sK[2048];
    __shared__ float part[256 * 4];
    __shared__ float sp[4 * 16];    // [(s*2+t)*16 + h]
    const float* base = QKV + (size_t)b * 2 * 3072;
#pragma unroll
    for (int i = 0; i < 8; i++) {
        int idx = tid + 256 * i;            // 0..2047
        int s = idx >> 10, j = idx & 1023;
        sQ[idx] = base[(size_t)s * 3072 + j];
        sK[idx] = base[(size_t)s * 3072 + 1024 + j];
    }
    __syncthreads();
    int h = tid & 15, u = tid >> 4;
    float p00 = 0.f, p01 = 0.f, p10 = 0.f, p11 = 0.f;
#pragma unroll
    for (int i = 0; i < 4; i++) {
        int j = h + 16 * u + 256 * i;     // columns with j%16 == h
        float q0 = sQ[j], q1 = sQ[1024 + j];
        float k0 = sK[j], k1 = sK[1024 + j];
        p00 += q0 * k0; p01 += q0 * k1;
        p10 += q1 * k0; p11 += q1 * k1;
    }
    part[tid * 4 + 0] = p00; part[tid * 4 + 1] = p01;
    part[tid * 4 + 2] = p10; part[tid * 4 + 3] = p11;
    __syncthreads();
    if (tid < 32) {
        int s = tid >> 4;
        int hh = tid & 15;
        float a0 = 0.f, a1 = 0.f;
#pragma unroll
        for (int uu = 0; uu < 16; uu++) {
            a0 += part[(uu * 16 + hh) * 4 + s * 2 + 0];
            a1 += part[(uu * 16 + hh) * 4 + s * 2 + 1];
        }
        a0 *= 0.125f; a1 *= 0.125f;           // / sqrt(64)
        float mx = fmaxf(a0, a1);
        float e0 = expf(a0 - mx), e1 = expf(a1 - mx);
        float inv = 1.f / (e0 + e1);
        sp[(s * 2 + 0) * 16 + hh] = e0 * inv;
        sp[(s * 2 + 1) * 16 + hh] = e1 * inv;
    }
    __syncthreads();
    float* op = O + (size_t)b * 2048;
#pragma unroll
    for (int i = 0; i < 4; i++) {
        int j = tid + 256 * i;
        int hh = j & 15;
        float v0 = base[2048 + j];           // s=0 V row
        float v1 = base[3072 + 2048 + j];    // s=1 V row
        op[j]        = rtf(sp[0 * 16 + hh] * v0 + sp[1 * 16 + hh] * v1);
        op[1024 + j] = rtf(sp[2 * 16 + hh] * v0 + sp[3 * 16 + hh] * v1);
    }
}

// ============================================================================
// TF32 mma.sync GEMM v2: CTA 128x256, 8 warps, warp tile 64x64 (mt4 x nt8).
// 3-stage cp.async, one __syncthreads per ktile. Operands pre-rounded to tf32.
// ============================================================================
#define TM 128
#define TN 256
#define BK 32
#define SROW 36
#define ASTF (TM * SROW)            // 4608 floats
#define BSTF (TN * SROW)            // 9216 floats
#define STF  (ASTF + BSTF)          // 13824 floats / stage
#define NST 3
#define GSMEM (NST * STF * 4)       // 165888 B

__device__ __forceinline__ void cpa16(float* sdst, const float* g) {
    uint32_t s = (uint32_t)__cvta_generic_to_shared(sdst);
    asm volatile("cp.async.cg.shared.global [%0], [%1], 16;\n" :: "r"(s), "l"(g));
}
__device__ __forceinline__ void mma8(float* d, const uint32_t* a, const uint32_t* b2) {
    asm volatile(
        "mma.sync.aligned.m16n8k8.row.col.f32.tf32.tf32.f32 "
        "{%0,%1,%2,%3}, {%4,%5,%6,%7}, {%8,%9}, {%0,%1,%2,%3};\n"
        : "+f"(d[0]), "+f"(d[1]), "+f"(d[2]), "+f"(d[3])
        : "r"(a[0]), "r"(a[1]), "r"(a[2]), "r"(a[3]), "r"(b2[0]), "r"(b2[1]));
}

__device__ __forceinline__ void load_stage(
    int tid, float* st, long kt,
    const float* __restrict__ A, long lda, long bm,
    const float* __restrict__ W, long ldw, long bn)
{
    float* sA = st;
    float* sB = st + ASTF;
    const float* Ak = A + kt * BK;
    const float* Wk = W + kt * BK;
#pragma unroll
    for (int i = 0; i < 4; i++) {            // A: 1024 chunks of 16B
        int idx = tid + 256 * i;
        int row = idx >> 3, c = (idx & 7) * 4;
        cpa16(&sA[row * SROW + c], Ak + (bm + row) * lda + c);
    }
#pragma unroll
    for (int i = 0; i < 8; i++) {            // B: 2048 chunks of 16B
        int idx = tid + 256 * i;
        int row = idx >> 3, c = (idx & 7) * 4;
        cpa16(&sB[row * SROW + c], Wk + (bn + row) * ldw + c);
    }
}

__global__ __launch_bounds__(256) void gemm_v2(
    const float* __restrict__ A, long lda,        // M x K (row-major)
    const float* __restrict__ W, long ldw,        // N x K (row-major)
    const float* __restrict__ bias,               // [N] or null
    const float* __restrict__ resid, long ldr,    // residual add or null
    float* __restrict__ C, long ldc,
    int K, int doTanh, int roundOut,
    // second parameter set, selected by blockIdx.z (for merged FFN pairs)
    const float* __restrict__ A2, const float* __restrict__ W2,
    const float* __restrict__ bias2, const float* __restrict__ resid2,
    float* __restrict__ C2)
{
    if (blockIdx.z) { A = A2; W = W2; bias = bias2; resid = resid2; C = C2; }
    extern __shared__ float sm[];
    int tid = threadIdx.x;
    int warp = tid >> 5, lane = tid & 31;
    int wm = warp >> 2, wn = warp & 3;             // 2(M) x 4(N) warps, tile 64x64
    long bm = (long)blockIdx.y * TM;
    long bn = (long)blockIdx.x * TN;

    float acc[4][8][4];
#pragma unroll
    for (int i = 0; i < 4; i++)
#pragma unroll
        for (int j = 0; j < 8; j++)
#pragma unroll
            for (int q = 0; q < 4; q++) acc[i][j][q] = 0.f;

    int rA = wm * 64 + (lane >> 2);
    int rB = wn * 64 + (lane >> 2);
    int cL = lane & 3;
    int nk = K / BK;

    // prologue: stages 0,1
    load_stage(tid, sm + 0 * STF, 0, A, lda, bm, W, ldw, bn);
    asm volatile("cp.async.commit_group;\n");
    load_stage(tid, sm + 1 * STF, 1, A, lda, bm, W, ldw, bn);
    asm volatile("cp.async.commit_group;\n");

    for (int kt = 0; kt < nk; kt++) {
        if (kt == nk - 1) asm volatile("cp.async.wait_group 0;\n");
        else              asm volatile("cp.async.wait_group 1;\n");
        __syncthreads();
        if (kt + 2 < nk) {
            load_stage(tid, sm + ((kt + 2) % NST) * STF, kt + 2, A, lda, bm, W, ldw, bn);
            asm volatile("cp.async.commit_group;\n");
        }
        const uint32_t* aS = (const uint32_t*)(sm + (kt % NST) * STF);
        const uint32_t* bS = aS + ASTF;
#pragma unroll
        for (int kk = 0; kk < BK; kk += 8) {
            uint32_t af[4][4], bf[8][2];
#pragma unroll
            for (int mt = 0; mt < 4; mt++) {
                const uint32_t* p = aS + (rA + mt * 16) * SROW + kk + cL;
                af[mt][0] = p[0];
                af[mt][1] = p[8 * SROW];
                af[mt][2] = p[4];
                af[mt][3] = p[8 * SROW + 4];
            }
#pragma unroll
            for (int nt = 0; nt < 8; nt++) {
                const uint32_t* p = bS + (rB + nt * 8) * SROW + kk + cL;
                bf[nt][0] = p[0];
                bf[nt][1] = p[4];
            }
#pragma unroll
            for (int mt = 0; mt < 4; mt++)
#pragma unroll
                for (int nt = 0; nt < 8; nt++)
                    mma8(acc[mt][nt], af[mt], bf[nt]);
        }
    }

    // epilogue: bias -> tanh -> residual -> (optional tf32 round)
#pragma unroll
    for (int mt = 0; mt < 4; mt++) {
        long row0 = bm + wm * 64 + mt * 16 + (lane >> 2);
#pragma unroll
        for (int nt = 0; nt < 8; nt++) {
            long col = bn + wn * 64 + nt * 8 + (lane & 3) * 2;
#pragma unroll
            for (int hh = 0; hh < 2; hh++) {
                long row = row0 + hh * 8;
                float x0 = acc[mt][nt][hh * 2 + 0];
                float x1 = acc[mt][nt][hh * 2 + 1];
                if (bias) { x0 += bias[col]; x1 += bias[col + 1]; }
                if (doTanh) { x0 = tanhf(x0); x1 = tanhf(x1); }
                if (resid) {
                    const float* rp = resid + row * ldr + col;
                    x0 += rp[0]; x1 += rp[1];
                }
                if (roundOut) { x0 = rtf(x0); x1 = rtf(x1); }
                float2 o; o.x = x0; o.y = x1;
                *reinterpret_cast<float2*>(C + row * ldc + col) = o;
            }
        }
    }
}

// ---------------- host launch ------------------------------------------------
static float* symaddr(const void* s) {
    void* p = nullptr;
    cudaGetSymbolAddress(&p, s);
    return (float*)p;
}

extern "C" void kernel_launch(void* const* d_in, const int* in_sizes, int n_in,
                              void* d_out, int out_size) {
    const float* input = (const float*)d_in[0];
    const float* Wq    = (const float*)d_in[1];
    const float* Wk    = (const float*)d_in[2];
    const float* Wv    = (const float*)d_in[3];
    const float* Wo    = (const float*)d_in[4];
    const float* ln1w  = (const float*)d_in[5];
    const float* ln1b  = (const float*)d_in[6];
    const float* ln2w  = (const float*)d_in[7];
    const float* ln2b  = (const float*)d_in[8];
    const float* f1w1  = (const float*)d_in[9];
    const float* f1b1  = (const float*)d_in[10];
    const float* f1w2  = (const float*)d_in[11];
    const float* f1b2  = (const float*)d_in[12];
    const float* f2w1  = (const float*)d_in[13];
    const float* f2b1  = (const float*)d_in[14];
    const float* f2w2  = (const float*)d_in[15];
    const float* f2b2  = (const float*)d_in[16];
    float* out = (float*)d_out;

    float* xs  = symaddr(g_xs);
    float* qkv = symaddr(g_qkv);
    float* cc  = symaddr(g_cc);
    float* o1  = symaddr(g_o1);
    float* os  = symaddr(g_os);
    float* h0  = symaddr(g_h0);
    float* h1  = symaddr(g_h1);
    float* wr  = symaddr(g_wr);

    const size_t M1 = 1024 * 1024;
    float* rQKVw = wr;            // 3M: Wq|Wk|Wv as one 3072x1024 matrix
    float* rWo   = wr + 3 * M1;
    float* rf1w1 = wr + 4 * M1;
    float* rf1w2 = wr + 6 * M1;
    float* rf2w1 = wr + 8 * M1;
    float* rf2w2 = wr + 10 * M1;

    cudaFuncSetAttribute(gemm_v2, cudaFuncAttributeMaxDynamicSharedMemorySize, GSMEM);

    // 0) round all weights to tf32 (one launch)
    round_all<<<(int)(12 * M1 / 1024), 256>>>(Wq, Wk, Wv, Wo, f1w1, f1w2, f2w1, f2w2, wr);

    // 1) LN1
    ln_kernel<<<B_DIM, 256>>>(input, ln1w, ln1b, xs);

    // 2) fused QKV projection: [16384 x 1024] @ [3072 x 1024]^T -> [16384 x 3072]
    dim3 gqkv(3 * E_DIM / TN, NROWS / TM);   // (12, 128)
    gemm_v2<<<gqkv, 256, GSMEM>>>(xs, E_DIM, rQKVw, E_DIM, nullptr, nullptr, 0,
                                  qkv, 3 * E_DIM, E_DIM, 0, 0,
                                  nullptr, nullptr, nullptr, nullptr, nullptr);

    // 3) attention -> concat
    attn_kernel<<<B_DIM, 256>>>(qkv, cc);

    // 4) Wo projection + residual: o1 = input + concat @ Wo^T
    dim3 gwo(E_DIM / TN, NROWS / TM);        // (4, 128)
    gemm_v2<<<gwo, 256, GSMEM>>>(cc, E_DIM, rWo, E_DIM, nullptr, input, E_DIM,
                                 o1, E_DIM, E_DIM, 0, 0,
                                 nullptr, nullptr, nullptr, nullptr, nullptr);

    // 5) LN2
    ln_kernel<<<B_DIM, 256>>>(o1, ln2w, ln2b, os);

    // 6) FFN layer 1, s=0 and s=1 merged via grid.z
    dim3 gf1(HID / TN, B_DIM / TM, 2);       // (8, 64, 2)
    gemm_v2<<<gf1, 256, GSMEM>>>(os, HID, rf1w1, E_DIM, f1b1, nullptr, 0,
                                 h0, HID, E_DIM, 1, 1,
                                 os + 1024, rf2w1, f2b1, nullptr, h1);

    // 7) FFN layer 2, s=0 and s=1 merged via grid.z (writes d_out directly)
    dim3 gf2(E_DIM / TN, B_DIM / TM, 2);     // (4, 64, 2)
    gemm_v2<<<gf2, 256, GSMEM>>>(h0, HID, rf1w2, HID, f1b2, o1, HID,
                                 out, HID, HID, 1, 0,
                                 h1, rf2w2, f2b2, o1 + 1024, out + 1024);
}

// round 11
// speedup vs baseline: 1.1157x; 1.1157x over previous
#include <cuda_runtime.h>
#include <math.h>
#include <stdint.h>

#define E_DIM 1024
#define B_DIM 8192
#define NROWS (B_DIM * 2)          // 16384
#define HID 2048

// ---------------- scratch (device globals; no allocations allowed) ----------
__device__ float g_xs [(size_t)NROWS * E_DIM];      // ln1 output (tf32-rounded)
__device__ float g_qkv[(size_t)NROWS * 3 * E_DIM];  // fused q|k|v, row stride 3072
__device__ float g_cc [(size_t)NROWS * E_DIM];      // attention concat (tf32-rounded)
__device__ float g_o1 [(size_t)NROWS * E_DIM];      // input + res (full fp32)
__device__ float g_os [(size_t)NROWS * E_DIM];      // ln2 output (tf32-rounded)
__device__ float g_h0 [(size_t)B_DIM * HID];        // ffn hidden s=0
__device__ float g_h1 [(size_t)B_DIM * HID];        // ffn hidden s=1
__device__ float g_wr [(size_t)12 * 1024 * 1024];   // tf32-rounded weights

__device__ __forceinline__ uint32_t f2tf(float f) {
    uint32_t r;
    asm volatile("cvt.rna.tf32.f32 %0, %1;" : "=r"(r) : "f"(f));
    return r;
}
__device__ __forceinline__ float rtf(float f) { return __uint_as_float(f2tf(f)); }

// ---------------- fused weight rounding: 12M floats in one launch -----------
__global__ void round_all(const float* __restrict__ Wq, const float* __restrict__ Wk,
                          const float* __restrict__ Wv, const float* __restrict__ Wo,
                          const float* __restrict__ f1w1, const float* __restrict__ f1w2,
                          const float* __restrict__ f2w1, const float* __restrict__ f2w2,
                          float* __restrict__ dst) {
    const size_t M1 = 1024 * 1024;
    size_t i4 = (size_t)blockIdx.x * 256 + threadIdx.x;   // float4 index
    size_t i = i4 * 4;                                    // element index < 12M
    const float* s; size_t off;
    if      (i <  1 * M1) { s = Wq;   off = 0; }
    else if (i <  2 * M1) { s = Wk;   off = 1 * M1; }
    else if (i <  3 * M1) { s = Wv;   off = 2 * M1; }
    else if (i <  4 * M1) { s = Wo;   off = 3 * M1; }
    else if (i <  6 * M1) { s = f1w1; off = 4 * M1; }
    else if (i <  8 * M1) { s = f1w2; off = 6 * M1; }
    else if (i < 10 * M1) { s = f2w1; off = 8 * M1; }
    else                  { s = f2w2; off = 10 * M1; }
    float4 v = *reinterpret_cast<const float4*>(s + (i - off));
    v.x = rtf(v.x); v.y = rtf(v.y); v.z = rtf(v.z); v.w = rtf(v.w);
    *reinterpret_cast<float4*>(dst + i) = v;
}

// ---------------- LayerNorm over joint (S=2, E=1024) = 2048 elems ----------
__global__ void ln_kernel(const float* __restrict__ x, const float* __restrict__ w,
                          const float* __restrict__ bb, float* __restrict__ y) {
    int b = blockIdx.x;
    int tid = threadIdx.x;
    const float* xr = x + (size_t)b * 2048;
    float v[8];
    float s = 0.f, s2 = 0.f;
#pragma unroll
    for (int i = 0; i < 8; i++) {
        float t = xr[tid + 256 * i];
        v[i] = t; s += t; s2 += t * t;
    }
#pragma unroll
    for (int o = 16; o; o >>= 1) {
        s  += __shfl_xor_sync(0xFFFFFFFFu, s,  o);
        s2 += __shfl_xor_sync(0xFFFFFFFFu, s2, o);
    }
    __shared__ float rs[8], rs2[8];
    __shared__ float mean_s, rstd_s;
    if ((tid & 31) == 0) { rs[tid >> 5] = s; rs2[tid >> 5] = s2; }
    __syncthreads();
    if (tid == 0) {
        float a = 0.f, a2 = 0.f;
#pragma unroll
        for (int i = 0; i < 8; i++) { a += rs[i]; a2 += rs2[i]; }
        float m = a * (1.f / 2048.f);
        float var = a2 * (1.f / 2048.f) - m * m;
        mean_s = m;
        rstd_s = rsqrtf(var + 1e-5f);
    }
    __syncthreads();
    float m = mean_s, r = rstd_s;
    float* yr = y + (size_t)b * 2048;
#pragma unroll
    for (int i = 0; i < 8; i++) {
        int j = tid + 256 * i;
        yr[j] = rtf((v[i] - m) * r * w[j] + bb[j]);
    }
}

// ---------------- Attention (S=2, H=16, NH=64), reads fused qkv -------------
__global__ void attn_kernel(const float* __restrict__ QKV, float* __restrict__ O) {
    int b = blockIdx.x;
    int tid = threadIdx.x;
    __shared__ float sQ[2048], sK[2048];
    __shared__ float part[256 * 4];
    __shared__ float sp[4 * 16];    // [(s*2+t)*16 + h]
    const float* base = QKV + (size_t)b * 2 * 3072;
#pragma unroll
    for (int i = 0; i < 8; i++) {
        int idx = tid + 256 * i;            // 0..2047
        int s = idx >> 10, j = idx & 1023;
        sQ[idx] = base[(size_t)s * 3072 + j];
        sK[idx] = base[(size_t)s * 3072 + 1024 + j];
    }
    __syncthreads();
    int h = tid & 15, u = tid >> 4;
    float p00 = 0.f, p01 = 0.f, p10 = 0.f, p11 = 0.f;
#pragma unroll
    for (int i = 0; i < 4; i++) {
        int j = h + 16 * u + 256 * i;     // columns with j%16 == h
        float q0 = sQ[j], q1 = sQ[1024 + j];
        float k0 = sK[j], k1 = sK[1024 + j];
        p00 += q0 * k0; p01 += q0 * k1;
        p10 += q1 * k0; p11 += q1 * k1;
    }
    part[tid * 4 + 0] = p00; part[tid * 4 + 1] = p01;
    part[tid * 4 + 2] = p10; part[tid * 4 + 3] = p11;
    __syncthreads();
    if (tid < 32) {
        int s = tid >> 4;
        int hh = tid & 15;
        float a0 = 0.f, a1 = 0.f;
#pragma unroll
        for (int uu = 0; uu < 16; uu++) {
            a0 += part[(uu * 16 + hh) * 4 + s * 2 + 0];
            a1 += part[(uu * 16 + hh) * 4 + s * 2 + 1];
        }
        a0 *= 0.125f; a1 *= 0.125f;           // / sqrt(64)
        float mx = fmaxf(a0, a1);
        float e0 = expf(a0 - mx), e1 = expf(a1 - mx);
        float inv = 1.f / (e0 + e1);
        sp[(s * 2 + 0) * 16 + hh] = e0 * inv;
        sp[(s * 2 + 1) * 16 + hh] = e1 * inv;
    }
    __syncthreads();
    float* op = O + (size_t)b * 2048;
#pragma unroll
    for (int i = 0; i < 4; i++) {
        int j = tid + 256 * i;
        int hh = j & 15;
        float v0 = base[2048 + j];           // s=0 V row
        float v1 = base[3072 + 2048 + j];    // s=1 V row
        op[j]        = rtf(sp[0 * 16 + hh] * v0 + sp[1 * 16 + hh] * v1);
        op[1024 + j] = rtf(sp[2 * 16 + hh] * v0 + sp[3 * 16 + hh] * v1);
    }
}

// ============================================================================
// TF32 mma.sync GEMM v3: CTA 128x128, 4 warps (128 thr), warp tile 64x64.
// 3-stage cp.async, one __syncthreads per ktile, 2 CTAs/SM resident.
// Crossbar/ktile: LDS 64KB + STS 32KB = 96KB < tensor ~973cyc -> tensor-bound.
// ============================================================================
#define TM 128
#define TN 128
#define BK 32
#define SROW 36
#define ASTF (TM * SROW)            // 4608 floats
#define BSTF (TN * SROW)            // 4608 floats
#define STF  (ASTF + BSTF)          // 9216 floats / stage
#define NST 3
#define GSMEM (NST * STF * 4)       // 110592 B -> 2 CTAs/SM

__device__ __forceinline__ void cpa16(float* sdst, const float* g) {
    uint32_t s = (uint32_t)__cvta_generic_to_shared(sdst);
    asm volatile("cp.async.cg.shared.global [%0], [%1], 16;\n" :: "r"(s), "l"(g));
}
__device__ __forceinline__ void mma8(float* d, const uint32_t* a, const uint32_t* b2) {
    asm volatile(
        "mma.sync.aligned.m16n8k8.row.col.f32.tf32.tf32.f32 "
        "{%0,%1,%2,%3}, {%4,%5,%6,%7}, {%8,%9}, {%0,%1,%2,%3};\n"
        : "+f"(d[0]), "+f"(d[1]), "+f"(d[2]), "+f"(d[3])
        : "r"(a[0]), "r"(a[1]), "r"(a[2]), "r"(a[3]), "r"(b2[0]), "r"(b2[1]));
}

__device__ __forceinline__ void load_stage(
    int tid, float* st, int kt,
    const float* __restrict__ A, int lda, int bm,
    const float* __restrict__ W, int ldw, int bn)
{
    float* sA = st;
    float* sB = st + ASTF;
    const float* Ak = A + (size_t)kt * BK;
    const float* Wk = W + (size_t)kt * BK;
#pragma unroll
    for (int i = 0; i < 8; i++) {            // A: 1024 chunks of 16B, 128 thr
        int idx = tid + 128 * i;
        int row = idx >> 3, c = (idx & 7) * 4;
        cpa16(&sA[row * SROW + c], Ak + (size_t)(bm + row) * lda + c);
    }
#pragma unroll
    for (int i = 0; i < 8; i++) {            // B: 1024 chunks of 16B
        int idx = tid + 128 * i;
        int row = idx >> 3, c = (idx & 7) * 4;
        cpa16(&sB[row * SROW + c], Wk + (size_t)(bn + row) * ldw + c);
    }
}

__global__ __launch_bounds__(128) void gemm_v3(
    const float* __restrict__ A, int lda,         // M x K (row-major)
    const float* __restrict__ W, int ldw,         // N x K (row-major)
    const float* __restrict__ bias,               // [N] or null
    const float* __restrict__ resid, int ldr,     // residual add or null
    float* __restrict__ C, int ldc,
    int K, int doTanh, int roundOut,
    // second parameter set, selected by blockIdx.z (for merged FFN pairs)
    const float* __restrict__ A2, const float* __restrict__ W2,
    const float* __restrict__ bias2, const float* __restrict__ resid2,
    float* __restrict__ C2)
{
    if (blockIdx.z) { A = A2; W = W2; bias = bias2; resid = resid2; C = C2; }
    extern __shared__ float sm[];
    int tid = threadIdx.x;
    int warp = tid >> 5, lane = tid & 31;
    int wm = warp >> 1, wn = warp & 1;             // 2(M) x 2(N) warps, tile 64x64
    int bm = blockIdx.y * TM;
    int bn = blockIdx.x * TN;

    float acc[4][8][4];
#pragma unroll
    for (int i = 0; i < 4; i++)
#pragma unroll
        for (int j = 0; j < 8; j++)
#pragma unroll
            for (int q = 0; q < 4; q++) acc[i][j][q] = 0.f;

    int rA = wm * 64 + (lane >> 2);
    int rB = wn * 64 + (lane >> 2);
    int cL = lane & 3;
    int nk = K / BK;

    // prologue: stages 0,1
    load_stage(tid, sm + 0 * STF, 0, A, lda, bm, W, ldw, bn);
    asm volatile("cp.async.commit_group;\n");
    load_stage(tid, sm + 1 * STF, 1, A, lda, bm, W, ldw, bn);
    asm volatile("cp.async.commit_group;\n");

    for (int kt = 0; kt < nk; kt++) {
        if (kt == nk - 1) asm volatile("cp.async.wait_group 0;\n");
        else              asm volatile("cp.async.wait_group 1;\n");
        __syncthreads();
        if (kt + 2 < nk) {
            load_stage(tid, sm + ((kt + 2) % NST) * STF, kt + 2, A, lda, bm, W, ldw, bn);
            asm volatile("cp.async.commit_group;\n");
        }
        const uint32_t* aS = (const uint32_t*)(sm + (kt % NST) * STF);
        const uint32_t* bS = aS + ASTF;
#pragma unroll
        for (int kk = 0; kk < BK; kk += 8) {
            uint32_t af[4][4], bf[8][2];
#pragma unroll
            for (int mt = 0; mt < 4; mt++) {
                const uint32_t* p = aS + (rA + mt * 16) * SROW + kk + cL;
                af[mt][0] = p[0];
                af[mt][1] = p[8 * SROW];
                af[mt][2] = p[4];
                af[mt][3] = p[8 * SROW + 4];
            }
#pragma unroll
            for (int nt = 0; nt < 8; nt++) {
                const uint32_t* p = bS + (rB + nt * 8) * SROW + kk + cL;
                bf[nt][0] = p[0];
                bf[nt][1] = p[4];
            }
#pragma unroll
            for (int mt = 0; mt < 4; mt++)
#pragma unroll
                for (int nt = 0; nt < 8; nt++)
                    mma8(acc[mt][nt], af[mt], bf[nt]);
        }
    }

    // epilogue: bias -> tanh -> residual -> (optional tf32 round)
#pragma unroll
    for (int mt = 0; mt < 4; mt++) {
        int row0 = bm + wm * 64 + mt * 16 + (lane >> 2);
#pragma unroll
        for (int nt = 0; nt < 8; nt++) {
            int col = bn + wn * 64 + nt * 8 + (lane & 3) * 2;
#pragma unroll
            for (int hh = 0; hh < 2; hh++) {
                int row = row0 + hh * 8;
                float x0 = acc[mt][nt][hh * 2 + 0];
                float x1 = acc[mt][nt][hh * 2 + 1];
                if (bias) { x0 += bias[col]; x1 += bias[col + 1]; }
                if (doTanh) { x0 = tanhf(x0); x1 = tanhf(x1); }
                if (resid) {
                    const float* rp = resid + (size_t)row * ldr + col;
                    x0 += rp[0]; x1 += rp[1];
                }
                if (roundOut) { x0 = rtf(x0); x1 = rtf(x1); }
                float2 o; o.x = x0; o.y = x1;
                *reinterpret_cast<float2*>(C + (size_t)row * ldc + col) = o;
            }
        }
    }
}

// ---------------- host launch ------------------------------------------------
static float* symaddr(const void* s) {
    void* p = nullptr;
    cudaGetSymbolAddress(&p, s);
    return (float*)p;
}

extern "C" void kernel_launch(void* const* d_in, const int* in_sizes, int n_in,
                              void* d_out, int out_size) {
    const float* input = (const float*)d_in[0];
    const float* Wq    = (const float*)d_in[1];
    const float* Wk    = (const float*)d_in[2];
    const float* Wv    = (const float*)d_in[3];
    const float* Wo    = (const float*)d_in[4];
    const float* ln1w  = (const float*)d_in[5];
    const float* ln1b  = (const float*)d_in[6];
    const float* ln2w  = (const float*)d_in[7];
    const float* ln2b  = (const float*)d_in[8];
    const float* f1w1  = (const float*)d_in[9];
    const float* f1b1  = (const float*)d_in[10];
    const float* f1w2  = (const float*)d_in[11];
    const float* f1b2  = (const float*)d_in[12];
    const float* f2w1  = (const float*)d_in[13];
    const float* f2b1  = (const float*)d_in[14];
    const float* f2w2  = (const float*)d_in[15];
    const float* f2b2  = (const float*)d_in[16];
    float* out = (float*)d_out;

    float* xs  = symaddr(g_xs);
    float* qkv = symaddr(g_qkv);
    float* cc  = symaddr(g_cc);
    float* o1  = symaddr(g_o1);
    float* os  = symaddr(g_os);
    float* h0  = symaddr(g_h0);
    float* h1  = symaddr(g_h1);
    float* wr  = symaddr(g_wr);

    const size_t M1 = 1024 * 1024;
    float* rQKVw = wr;            // 3M: Wq|Wk|Wv as one 3072x1024 matrix
    float* rWo   = wr + 3 * M1;
    float* rf1w1 = wr + 4 * M1;
    float* rf1w2 = wr + 6 * M1;
    float* rf2w1 = wr + 8 * M1;
    float* rf2w2 = wr + 10 * M1;

    cudaFuncSetAttribute(gemm_v3, cudaFuncAttributeMaxDynamicSharedMemorySize, GSMEM);

    // 0) round all weights to tf32 (one launch)
    round_all<<<(int)(12 * M1 / 1024), 256>>>(Wq, Wk, Wv, Wo, f1w1, f1w2, f2w1, f2w2, wr);

    // 1) LN1
    ln_kernel<<<B_DIM, 256>>>(input, ln1w, ln1b, xs);

    // 2) fused QKV projection: [16384 x 1024] @ [3072 x 1024]^T -> [16384 x 3072]
    dim3 gqkv(3 * E_DIM / TN, NROWS / TM);   // (24, 128)
    gemm_v3<<<gqkv, 128, GSMEM>>>(xs, E_DIM, rQKVw, E_DIM, nullptr, nullptr, 0,
                                  qkv, 3 * E_DIM, E_DIM, 0, 0,
                                  nullptr, nullptr, nullptr, nullptr, nullptr);

    // 3) attention -> concat
    attn_kernel<<<B_DIM, 256>>>(qkv, cc);

    // 4) Wo projection + residual: o1 = input + concat @ Wo^T
    dim3 gwo(E_DIM / TN, NROWS / TM);        // (8, 128)
    gemm_v3<<<gwo, 128, GSMEM>>>(cc, E_DIM, rWo, E_DIM, nullptr, input, E_DIM,
                                 o1, E_DIM, E_DIM, 0, 0,
                                 nullptr, nullptr, nullptr, nullptr, nullptr);

    // 5) LN2
    ln_kernel<<<B_DIM, 256>>>(o1, ln2w, ln2b, os);

    // 6) FFN layer 1, s=0 and s=1 merged via grid.z
    dim3 gf1(HID / TN, B_DIM / TM, 2);       // (16, 64, 2)
    gemm_v3<<<gf1, 128, GSMEM>>>(os, HID, rf1w1, E_DIM, f1b1, nullptr, 0,
                                 h0, HID, E_DIM, 1, 1,
                                 os + 1024, rf2w1, f2b1, nullptr, h1);

    // 7) FFN layer 2, s=0 and s=1 merged via grid.z (writes d_out directly)
    dim3 gf2(E_DIM / TN, B_DIM / TM, 2);     // (8, 64, 2)
    gemm_v3<<<gf2, 128, GSMEM>>>(h0, HID, rf1w2, HID, f1b2, o1, HID,
                                 out, HID, HID, 1, 0,
                                 h1, rf2w2, f2b2, o1 + 1024, out + 1024);
}